// round 1
// baseline (speedup 1.0000x reference)
#include <cuda_runtime.h>
#include <cstdint>

#define NN 100000   // nodes
#define NE 200000   // edges
#define DD 256      // feature dim
#define NB 2        // num basis
#define NC 8        // num classes

// Scratch: T[b][n][d] = sum_k h_src[n,k] * P[b][k][d]   (2 * 100000 * 256 fp32 = 204.8 MB)
__device__ float g_T[(size_t)NB * NN * DD];

// ---------------------------------------------------------------------------
// Kernel 1: T[b] = h_src @ P[b]
// Classic 128x128x8 fp32 tiled GEMM, 256 threads, 8x8 microtiles.
// grid = (ceil(NN/128), DD/128, NB)
// ---------------------------------------------------------------------------
constexpr int BM = 128, BN = 128, BK = 8, TM = 8, TN = 8;

__global__ __launch_bounds__(256, 2)
void sgemm_kernel(const float* __restrict__ A,   // [NN, DD] row-major
                  const float* __restrict__ P)   // [NB, DD, DD]
{
    const int b = blockIdx.z;
    const float* B = P + (size_t)b * DD * DD;
    float* C = &g_T[(size_t)b * NN * DD];

    const int mBlock = blockIdx.x * BM;
    const int nBlock = blockIdx.y * BN;

    __shared__ float As[BK][BM];
    __shared__ float Bs[BK][BN];

    const int tid = threadIdx.x;
    const int tRow = (tid / 16) * TM;   // 0..120
    const int tCol = (tid % 16) * TN;   // 0..120

    // A tile loader: 128x8 floats = 256 float4 (one per thread)
    const int aRow = tid / 2;
    const int aCol = (tid % 2) * 4;
    // B tile loader: 8x128 floats = 256 float4 (one per thread)
    const int bRow = tid / 32;
    const int bCol = (tid % 32) * 4;

    float acc[TM][TN];
    #pragma unroll
    for (int i = 0; i < TM; i++)
        #pragma unroll
        for (int j = 0; j < TN; j++)
            acc[i][j] = 0.0f;

    float aReg[TM], bReg[TN];

    for (int k0 = 0; k0 < DD; k0 += BK) {
        // load A tile (guard M tail: NN % 128 != 0)
        const int gRow = mBlock + aRow;
        float4 av = make_float4(0.f, 0.f, 0.f, 0.f);
        if (gRow < NN)
            av = *reinterpret_cast<const float4*>(A + (size_t)gRow * DD + k0 + aCol);
        As[aCol + 0][aRow] = av.x;
        As[aCol + 1][aRow] = av.y;
        As[aCol + 2][aRow] = av.z;
        As[aCol + 3][aRow] = av.w;

        // load B tile (always in-bounds: DD=256 multiple of tiles)
        const float4 bv = *reinterpret_cast<const float4*>(
            B + (size_t)(k0 + bRow) * DD + nBlock + bCol);
        *reinterpret_cast<float4*>(&Bs[bRow][bCol]) = bv;

        __syncthreads();

        #pragma unroll
        for (int k = 0; k < BK; k++) {
            #pragma unroll
            for (int i = 0; i < TM; i++) aReg[i] = As[k][tRow + i];
            #pragma unroll
            for (int j = 0; j < TN; j++) bReg[j] = Bs[k][tCol + j];
            #pragma unroll
            for (int i = 0; i < TM; i++)
                #pragma unroll
                for (int j = 0; j < TN; j++)
                    acc[i][j] = fmaf(aReg[i], bReg[j], acc[i][j]);
        }
        __syncthreads();
    }

    // write back
    #pragma unroll
    for (int i = 0; i < TM; i++) {
        const int gRow = mBlock + tRow + i;
        if (gRow < NN) {
            #pragma unroll
            for (int j = 0; j < TN; j += 4) {
                float4 v = make_float4(acc[i][j], acc[i][j + 1],
                                       acc[i][j + 2], acc[i][j + 3]);
                *reinterpret_cast<float4*>(C + (size_t)gRow * DD + nBlock + tCol + j) = v;
            }
        }
    }
}

// ---------------------------------------------------------------------------
// Kernel 2: per edge e  s_b = T_b[u_e] . h_dst[v_e];  out[e,c] = sum_b W[c,b] s_b
// One warp per edge. 256-dim dot via float4 (2 float4 per lane), shuffle reduce.
// ---------------------------------------------------------------------------
__global__ __launch_bounds__(256)
void edge_kernel(const float* __restrict__ h_dst,
                 const int*   __restrict__ u_idx,
                 const int*   __restrict__ v_idx,
                 const float* __restrict__ W,     // [NC, NB]
                 float*       __restrict__ out)   // [NE, NC]
{
    const int warp = (blockIdx.x * blockDim.x + threadIdx.x) >> 5;
    const int lane = threadIdx.x & 31;
    if (warp >= NE) return;

    const int u = u_idx[warp];
    const int v = v_idx[warp];

    const float4* t0 = reinterpret_cast<const float4*>(&g_T[(size_t)u * DD]);
    const float4* t1 = reinterpret_cast<const float4*>(&g_T[((size_t)NN + u) * DD]);
    const float4* iv = reinterpret_cast<const float4*>(h_dst + (size_t)v * DD);

    float s0 = 0.0f, s1 = 0.0f;
    #pragma unroll
    for (int r = 0; r < 2; r++) {
        const int idx = lane + r * 32;   // 64 float4 = 256 floats
        const float4 a0 = t0[idx];
        const float4 a1 = t1[idx];
        const float4 c  = iv[idx];
        s0 += a0.x * c.x + a0.y * c.y + a0.z * c.z + a0.w * c.w;
        s1 += a1.x * c.x + a1.y * c.y + a1.z * c.z + a1.w * c.w;
    }

    #pragma unroll
    for (int off = 16; off; off >>= 1) {
        s0 += __shfl_xor_sync(0xffffffff, s0, off);
        s1 += __shfl_xor_sync(0xffffffff, s1, off);
    }

    if (lane < NC) {
        out[(size_t)warp * NC + lane] = W[lane * NB + 0] * s0 + W[lane * NB + 1] * s1;
    }
}

// ---------------------------------------------------------------------------
extern "C" void kernel_launch(void* const* d_in, const int* in_sizes, int n_in,
                              void* d_out, int out_size)
{
    const float* h_src = (const float*)d_in[0];
    const float* h_dst = (const float*)d_in[1];
    const int*   u_idx = (const int*)  d_in[2];
    const int*   v_idx = (const int*)  d_in[3];
    const float* P     = (const float*)d_in[4];
    const float* W     = (const float*)d_in[5];
    float* out = (float*)d_out;

    dim3 g1((NN + BM - 1) / BM, DD / BN, NB);   // (782, 2, 2)
    sgemm_kernel<<<g1, 256>>>(h_src, P);

    const int warps_total = NE;
    const int threads = 256;
    const int blocks = (warps_total * 32 + threads - 1) / threads;  // 25000
    edge_kernel<<<blocks, threads>>>(h_dst, u_idx, v_idx, W, out);
}

// round 4
// speedup vs baseline: 2.6024x; 2.6024x over previous
#include <cuda_runtime.h>
#include <cstdint>

#define NN 100000   // nodes
#define NE 200000   // edges
#define DD 256      // feature dim
#define NB 2        // num basis
#define NC 8        // num classes

// Scratch: T[n][b*256+d]  (bases interleaved per node for edge-kernel locality)
// 100000 * 512 fp32 = 204.8 MB
__device__ float g_T[(size_t)NN * (NB * DD)];

// ---------------------------------------------------------------------------
// tf32 helpers
// ---------------------------------------------------------------------------
__device__ __forceinline__ uint32_t f2tf32(float x) {
    uint32_t r;
    asm("cvt.rna.tf32.f32 %0, %1;" : "=r"(r) : "f"(x));
    return r;
}

__device__ __forceinline__ void mma16n8k8(float c[4], const uint32_t a[4],
                                          const uint32_t b[2]) {
    asm volatile(
        "mma.sync.aligned.m16n8k8.row.col.f32.tf32.tf32.f32 "
        "{%0,%1,%2,%3}, {%4,%5,%6,%7}, {%8,%9}, {%0,%1,%2,%3};"
        : "+f"(c[0]), "+f"(c[1]), "+f"(c[2]), "+f"(c[3])
        : "r"(a[0]), "r"(a[1]), "r"(a[2]), "r"(a[3]), "r"(b[0]), "r"(b[1]));
}

// ---------------------------------------------------------------------------
// Kernel 1: T[:, b*256:(b+1)*256] = h_src @ P[b]   as one GEMM [NN,256]x[256,512]
// 128x128x16 tiles, 2-stage cp.async pipeline, 8 warps (2x4), 64x32 warp tiles.
// grid = (ceil(NN/128)=782, 512/128=4)
// ---------------------------------------------------------------------------
constexpr int BM = 128, BN = 128, BK = 16;
constexpr int AS = 20;    // A smem row stride (pad 4) -> conflict-free frag loads
constexpr int BS = 136;   // B smem row stride (pad 8) -> conflict-free frag loads

__global__ __launch_bounds__(256)
void gemm_tf32(const float* __restrict__ A,   // [NN, 256] row-major
               const float* __restrict__ P)   // [NB, 256, 256]
{
    __shared__ float As[2][BM * AS];
    __shared__ float Bs[2][BK * BS];

    const int mBlock = blockIdx.x * BM;
    const int nBlock = blockIdx.y * BN;
    // block's 128 columns lie entirely inside one basis (256-aligned split)
    const int basis = nBlock >> 8;
    const float* Bmat = P + ((size_t)basis << 16) + (nBlock & 255);

    const int tid  = threadIdx.x;
    const int lane = tid & 31;
    const int warp = tid >> 5;
    const int wm = warp >> 2;          // 0..1
    const int wn = warp & 3;           // 0..3
    const int mBase = wm * 64;
    const int nBase = wn * 32;
    const int grp = lane >> 2;         // 0..7
    const int tig = lane & 3;          // 0..3

    // cp.async loaders: A tile 128x16 = 512 x 16B chunks; B tile 16x128 = 512 chunks
    const int aChunkR0 = tid >> 2;             // chunk -> row
    const int aChunkC0 = (tid & 3) * 4;        //        -> col
    const int bChunkR0 = tid >> 5;
    const int bChunkC0 = (tid & 31) * 4;

    auto loadStage = [&](int s, int k0) {
        #pragma unroll
        for (int i = 0; i < 2; i++) {
            const int r = aChunkR0 + i * 64;   // +64 rows
            const int c = aChunkC0;
            uint32_t dst = (uint32_t)__cvta_generic_to_shared(&As[s][r * AS + c]);
            const float* src = A + (size_t)(mBlock + r) * DD + k0 + c;
            const int sz = (mBlock + r) < NN ? 16 : 0;   // zero-fill M tail
            asm volatile("cp.async.cg.shared.global [%0], [%1], 16, %2;"
                         :: "r"(dst), "l"(src), "r"(sz));
        }
        #pragma unroll
        for (int i = 0; i < 2; i++) {
            const int r = bChunkR0 + i * 8;    // +8 rows
            const int c = bChunkC0;
            uint32_t dst = (uint32_t)__cvta_generic_to_shared(&Bs[s][r * BS + c]);
            const float* src = Bmat + (size_t)(k0 + r) * DD + c;
            asm volatile("cp.async.cg.shared.global [%0], [%1], 16;"
                         :: "r"(dst), "l"(src));
        }
        asm volatile("cp.async.commit_group;");
    };

    float acc[4][4][4];
    #pragma unroll
    for (int i = 0; i < 4; i++)
        #pragma unroll
        for (int j = 0; j < 4; j++)
            #pragma unroll
            for (int r = 0; r < 4; r++) acc[i][j][r] = 0.0f;

    loadStage(0, 0);

    const int KT = DD / BK;   // 16
    for (int it = 0; it < KT; ++it) {
        if (it + 1 < KT) {
            loadStage((it + 1) & 1, (it + 1) * BK);
            asm volatile("cp.async.wait_group 1;");   // current stage ready
        } else {
            asm volatile("cp.async.wait_group 0;");   // drain: last stage ready
        }
        __syncthreads();

        const float* as = As[it & 1];
        const float* bs = Bs[it & 1];

        #pragma unroll
        for (int kk = 0; kk < 2; kk++) {
            const int k = kk * 8;
            uint32_t af[4][4];
            #pragma unroll
            for (int i = 0; i < 4; i++) {
                const int r = mBase + i * 16 + grp;
                af[i][0] = f2tf32(as[r * AS + k + tig]);
                af[i][1] = f2tf32(as[(r + 8) * AS + k + tig]);
                af[i][2] = f2tf32(as[r * AS + k + tig + 4]);
                af[i][3] = f2tf32(as[(r + 8) * AS + k + tig + 4]);
            }
            uint32_t bf[4][2];
            #pragma unroll
            for (int j = 0; j < 4; j++) {
                const int cc = nBase + j * 8 + grp;
                bf[j][0] = f2tf32(bs[(k + tig) * BS + cc]);
                bf[j][1] = f2tf32(bs[(k + tig + 4) * BS + cc]);
            }
            #pragma unroll
            for (int i = 0; i < 4; i++)
                #pragma unroll
                for (int j = 0; j < 4; j++)
                    mma16n8k8(acc[i][j], af[i], bf[j]);
        }
        __syncthreads();
    }

    // epilogue: write T rows (stride 512)
    #pragma unroll
    for (int i = 0; i < 4; i++) {
        const int row0 = mBlock + mBase + i * 16 + grp;
        #pragma unroll
        for (int j = 0; j < 4; j++) {
            const int col = nBlock + nBase + j * 8 + tig * 2;
            if (row0 < NN) {
                float2 v0 = make_float2(acc[i][j][0], acc[i][j][1]);
                *reinterpret_cast<float2*>(&g_T[(size_t)row0 * 512 + col]) = v0;
            }
            if (row0 + 8 < NN) {
                float2 v1 = make_float2(acc[i][j][2], acc[i][j][3]);
                *reinterpret_cast<float2*>(&g_T[(size_t)(row0 + 8) * 512 + col]) = v1;
            }
        }
    }
}

// ---------------------------------------------------------------------------
// Kernel 2: per edge e:  s_b = T[u_e, b*256:].h_dst[v_e];  out[e,c]=sum_b W[c,b] s_b
// One warp per edge, float4 dots + shuffle reduce.  (HBM-roofline bound.)
// ---------------------------------------------------------------------------
__global__ __launch_bounds__(256)
void edge_kernel(const float* __restrict__ h_dst,
                 const int*   __restrict__ u_idx,
                 const int*   __restrict__ v_idx,
                 const float* __restrict__ W,     // [NC, NB]
                 float*       __restrict__ out)   // [NE, NC]
{
    const int warp = (blockIdx.x * blockDim.x + threadIdx.x) >> 5;
    const int lane = threadIdx.x & 31;
    if (warp >= NE) return;

    const int u = u_idx[warp];
    const int v = v_idx[warp];

    const float4* t0 = reinterpret_cast<const float4*>(&g_T[(size_t)u * 512]);
    const float4* t1 = t0 + (DD / 4);
    const float4* iv = reinterpret_cast<const float4*>(h_dst + (size_t)v * DD);

    float s0 = 0.0f, s1 = 0.0f;
    #pragma unroll
    for (int r = 0; r < 2; r++) {
        const int idx = lane + r * 32;
        const float4 a0 = t0[idx];
        const float4 a1 = t1[idx];
        const float4 c  = iv[idx];
        s0 += a0.x * c.x + a0.y * c.y + a0.z * c.z + a0.w * c.w;
        s1 += a1.x * c.x + a1.y * c.y + a1.z * c.z + a1.w * c.w;
    }

    #pragma unroll
    for (int off = 16; off; off >>= 1) {
        s0 += __shfl_xor_sync(0xffffffff, s0, off);
        s1 += __shfl_xor_sync(0xffffffff, s1, off);
    }

    if (lane < NC) {
        out[(size_t)warp * NC + lane] = W[lane * NB + 0] * s0 + W[lane * NB + 1] * s1;
    }
}

// ---------------------------------------------------------------------------
extern "C" void kernel_launch(void* const* d_in, const int* in_sizes, int n_in,
                              void* d_out, int out_size)
{
    const float* h_src = (const float*)d_in[0];
    const float* h_dst = (const float*)d_in[1];
    const int*   u_idx = (const int*)  d_in[2];
    const int*   v_idx = (const int*)  d_in[3];
    const float* P     = (const float*)d_in[4];
    const float* W     = (const float*)d_in[5];
    float* out = (float*)d_out;

    dim3 g1((NN + BM - 1) / BM, (NB * DD) / BN);   // (782, 4)
    gemm_tf32<<<g1, 256>>>(h_src, P);

    const int blocks = (NE * 32 + 255) / 256;      // 25000
    edge_kernel<<<blocks, 256>>>(h_dst, u_idx, v_idx, W, out);
}

// round 8
// speedup vs baseline: 3.8640x; 1.4848x over previous
#include <cuda_runtime.h>
#include <cuda_fp16.h>
#include <cstdint>

#define NN 100000   // nodes
#define NE 200000   // edges
#define DD 256      // feature dim
#define NC 8        // num classes

// T[n][b*256+d] in fp16: 100000 x 512 = 102.4 MB
__device__ __half g_Th[(size_t)NN * 512];
// Pth[b*256+n][k] = fp16(P[b][k][n]) : 512 x 256 = 256 KB
__device__ __half g_Pth[512 * 256];

// ---------------------------------------------------------------------------
// Kernel 0: transpose + fp16-convert P  (tiny: 131072 elements)
// ---------------------------------------------------------------------------
__global__ void prep_p(const float* __restrict__ P) {
    const int idx = blockIdx.x * 256 + threadIdx.x;   // over 512*256
    const int bk = idx >> 8;          // b*256 + k
    const int n  = idx & 255;
    const int b  = bk >> 8;
    const int k  = bk & 255;
    g_Pth[(((size_t)b * 256 + n) << 8) | k] = __float2half_rn(P[idx]);
}

// ---------------------------------------------------------------------------
// Kernel 1: T = h_src @ [P0 | P1]  via mma.sync.m16n8k16 fp16 (fp32 accum).
// [NN,256] x [256,512].  BM=128, BN=128, BK=32 halfs.  8 warps (2x4), 64x32
// warp tiles.  B via cp.async from pre-converted g_Pth; A converted f32->f16
// in the producer.  grid = (4 n-tiles, 782 m-tiles): n fastest => the 4 CTAs
// sharing an A tile are launch-adjacent => A is L2-resident after first read.
// ---------------------------------------------------------------------------
constexpr int BM = 128, BN = 128, BKH = 32;
constexpr int SAH = 40;   // smem row stride in halfs (pad 8) -> conflict-free frags

__device__ __forceinline__ void mma16816(float c[4], const uint32_t a[4],
                                         const uint32_t b[2]) {
    asm volatile(
        "mma.sync.aligned.m16n8k16.row.col.f32.f16.f16.f32 "
        "{%0,%1,%2,%3}, {%4,%5,%6,%7}, {%8,%9}, {%0,%1,%2,%3};"
        : "+f"(c[0]), "+f"(c[1]), "+f"(c[2]), "+f"(c[3])
        : "r"(a[0]), "r"(a[1]), "r"(a[2]), "r"(a[3]), "r"(b[0]), "r"(b[1]));
}

__global__ __launch_bounds__(256)
void gemm_f16(const float* __restrict__ A)         // h_src [NN, 256]
{
    __shared__ __half As[2][BM * SAH];   // 10 KB each
    __shared__ __half Bs[2][BN * SAH];   // 10 KB each   (total 40 KB)

    const int tid  = threadIdx.x;
    const int lane = tid & 31;
    const int warp = tid >> 5;
    const int wm = warp >> 2;            // 0..1
    const int wn = warp & 3;             // 0..3
    const int mBase = wm * 64;
    const int nBase = wn * 32;
    const int grp = lane >> 2;           // 0..7
    const int tig = lane & 3;            // 0..3

    const int nBlock = blockIdx.x * BN;
    const int mBlock = blockIdx.y * BM;
    const __half* Brow0 = g_Pth + (size_t)nBlock * 256;

    // A producer: 128 rows x 32 floats -> fp16.  1024 segs of 4 floats; 4/thread.
    auto loadA = [&](int s, int k0) {
        #pragma unroll
        for (int j = 0; j < 4; j++) {
            const int q = tid + j * 256;
            const int row = q >> 3;
            const int seg = q & 7;
            const int gr = mBlock + row;
            float4 v = make_float4(0.f, 0.f, 0.f, 0.f);
            if (gr < NN)
                v = *reinterpret_cast<const float4*>(A + (size_t)gr * DD + k0 + seg * 4);
            __half2* dst = reinterpret_cast<__half2*>(&As[s][row * SAH + seg * 4]);
            dst[0] = __floats2half2_rn(v.x, v.y);
            dst[1] = __floats2half2_rn(v.z, v.w);
        }
    };
    // B producer: 128 rows (n) x 32 halfs (k); 64B/row = 4 x 16B chunks.
    auto loadB = [&](int s, int k0) {
        #pragma unroll
        for (int j = 0; j < 2; j++) {
            const int q = tid + j * 256;
            const int row = q >> 2;
            const int ch = q & 3;
            uint32_t dst = (uint32_t)__cvta_generic_to_shared(&Bs[s][row * SAH + ch * 8]);
            const __half* src = Brow0 + (size_t)row * 256 + k0 + ch * 8;
            asm volatile("cp.async.cg.shared.global [%0], [%1], 16;"
                         :: "r"(dst), "l"(src));
        }
        asm volatile("cp.async.commit_group;");
    };

    float acc[4][4][4];
    #pragma unroll
    for (int i = 0; i < 4; i++)
        #pragma unroll
        for (int j = 0; j < 4; j++)
            #pragma unroll
            for (int r = 0; r < 4; r++) acc[i][j][r] = 0.0f;

    loadA(0, 0);
    loadB(0, 0);

    const int KT = DD / BKH;   // 8
    for (int it = 0; it < KT; ++it) {
        if (it + 1 < KT) {
            loadA((it + 1) & 1, (it + 1) * BKH);
            loadB((it + 1) & 1, (it + 1) * BKH);
            asm volatile("cp.async.wait_group 1;");
        } else {
            asm volatile("cp.async.wait_group 0;");
        }
        __syncthreads();

        const __half* as = As[it & 1];
        const __half* bs = Bs[it & 1];

        #pragma unroll
        for (int kk = 0; kk < 2; kk++) {
            const int kb = kk * 16;
            uint32_t af[4][4];
            #pragma unroll
            for (int i = 0; i < 4; i++) {
                const int r = mBase + i * 16 + grp;
                af[i][0] = *reinterpret_cast<const uint32_t*>(&as[r * SAH + kb + 2 * tig]);
                af[i][1] = *reinterpret_cast<const uint32_t*>(&as[(r + 8) * SAH + kb + 2 * tig]);
                af[i][2] = *reinterpret_cast<const uint32_t*>(&as[r * SAH + kb + 2 * tig + 8]);
                af[i][3] = *reinterpret_cast<const uint32_t*>(&as[(r + 8) * SAH + kb + 2 * tig + 8]);
            }
            uint32_t bf[4][2];
            #pragma unroll
            for (int j = 0; j < 4; j++) {
                const int rb = nBase + j * 8 + grp;
                bf[j][0] = *reinterpret_cast<const uint32_t*>(&bs[rb * SAH + kb + 2 * tig]);
                bf[j][1] = *reinterpret_cast<const uint32_t*>(&bs[rb * SAH + kb + 2 * tig + 8]);
            }
            #pragma unroll
            for (int i = 0; i < 4; i++)
                #pragma unroll
                for (int j = 0; j < 4; j++)
                    mma16816(acc[i][j], af[i], bf[j]);
        }
        __syncthreads();
    }

    // epilogue: write fp16 T rows (stride 512)
    #pragma unroll
    for (int i = 0; i < 4; i++) {
        const int row0 = mBlock + mBase + i * 16 + grp;
        #pragma unroll
        for (int j = 0; j < 4; j++) {
            const int col = nBlock + nBase + j * 8 + tig * 2;
            if (row0 < NN)
                *reinterpret_cast<__half2*>(&g_Th[(size_t)row0 * 512 + col]) =
                    __floats2half2_rn(acc[i][j][0], acc[i][j][1]);
            if (row0 + 8 < NN)
                *reinterpret_cast<__half2*>(&g_Th[(size_t)(row0 + 8) * 512 + col]) =
                    __floats2half2_rn(acc[i][j][2], acc[i][j][3]);
        }
    }
}

// ---------------------------------------------------------------------------
// Kernel 2: per edge e:  s_b = T[u_e, b*256:] . h_dst[v_e];  out = W combine.
// One warp per edge; T in fp16 (1KB/basis-pair), h_dst fp32, math in fp32.
// ---------------------------------------------------------------------------
__global__ __launch_bounds__(256)
void edge_kernel(const float* __restrict__ h_dst,
                 const int*   __restrict__ u_idx,
                 const int*   __restrict__ v_idx,
                 const float* __restrict__ W,     // [NC, 2]
                 float*       __restrict__ out)   // [NE, NC]
{
    const int warp = (blockIdx.x * blockDim.x + threadIdx.x) >> 5;
    const int lane = threadIdx.x & 31;
    if (warp >= NE) return;

    const int u = u_idx[warp];
    const int v = v_idx[warp];

    const __half* t = g_Th + (size_t)u * 512;
    const float4* iv = reinterpret_cast<const float4*>(h_dst + (size_t)v * DD);

    const uint4 p0 = *reinterpret_cast<const uint4*>(t + lane * 8);         // basis 0
    const uint4 p1 = *reinterpret_cast<const uint4*>(t + 256 + lane * 8);   // basis 1
    const float4 c0 = iv[2 * lane];
    const float4 c1 = iv[2 * lane + 1];

    const __half2* h0 = reinterpret_cast<const __half2*>(&p0);
    const __half2* h1 = reinterpret_cast<const __half2*>(&p1);

    float s0 = 0.0f, s1 = 0.0f;
    float2 f;
    f = __half22float2(h0[0]); s0 += f.x * c0.x + f.y * c0.y;
    f = __half22float2(h0[1]); s0 += f.x * c0.z + f.y * c0.w;
    f = __half22float2(h0[2]); s0 += f.x * c1.x + f.y * c1.y;
    f = __half22float2(h0[3]); s0 += f.x * c1.z + f.y * c1.w;
    f = __half22float2(h1[0]); s1 += f.x * c0.x + f.y * c0.y;
    f = __half22float2(h1[1]); s1 += f.x * c0.z + f.y * c0.w;
    f = __half22float2(h1[2]); s1 += f.x * c1.x + f.y * c1.y;
    f = __half22float2(h1[3]); s1 += f.x * c1.z + f.y * c1.w;

    #pragma unroll
    for (int off = 16; off; off >>= 1) {
        s0 += __shfl_xor_sync(0xffffffff, s0, off);
        s1 += __shfl_xor_sync(0xffffffff, s1, off);
    }

    if (lane < NC) {
        out[(size_t)warp * NC + lane] = W[lane * 2 + 0] * s0 + W[lane * 2 + 1] * s1;
    }
}

// ---------------------------------------------------------------------------
extern "C" void kernel_launch(void* const* d_in, const int* in_sizes, int n_in,
                              void* d_out, int out_size)
{
    const float* h_src = (const float*)d_in[0];
    const float* h_dst = (const float*)d_in[1];
    const int*   u_idx = (const int*)  d_in[2];
    const int*   v_idx = (const int*)  d_in[3];
    const float* P     = (const float*)d_in[4];
    const float* W     = (const float*)d_in[5];
    float* out = (float*)d_out;

    prep_p<<<512, 256>>>(P);

    dim3 g1(512 / BN, (NN + BM - 1) / BM);         // (4, 782): n-tile fastest
    gemm_f16<<<g1, 256>>>(h_src);

    const int blocks = (NE * 32 + 255) / 256;      // 25000
    edge_kernel<<<blocks, 256>>>(h_dst, u_idx, v_idx, W, out);
}